// round 1
// baseline (speedup 1.0000x reference)
#include <cuda_runtime.h>
#include <math.h>

// ConvLSTM: T=16, B=4, Cin=32, HID=64, H=W=64, 3x3 SAME convs.
// One fused kernel per timestep: gates = conv(x_t; w_x2h) + conv(h_{t-1}; w_h2h) + b_x2h + b_h2h
// then LSTM pointwise. h_{t-1} read from previous output slice; c kept in device scratch.

#define T_   16
#define B_   4
#define CIN  32
#define HID  64
#define HH   64
#define WW   64
#define TILE 32
#define ICC  4
#define PATCH 34   // 32 + 2 halo

// cell-state scratch: [B, HID, H, W] = 4 MB
__device__ float g_c[B_ * HID * HH * WW];

__device__ __forceinline__ float sigmoidf_(float v) {
    return 1.f / (1.f + __expf(-v));
}

__global__ __launch_bounds__(256, 2)
void convlstm_step(const float* __restrict__ x_t,     // [B, CIN, H, W]
                   const float* __restrict__ h_prev,  // [B, HID, H, W] or unused when first
                   const float* __restrict__ w_x2h,   // [4*HID, CIN, 3, 3]
                   const float* __restrict__ w_h2h,   // [4*HID, HID, 3, 3]
                   const float* __restrict__ b_x2h,   // [4*HID]
                   const float* __restrict__ b_h2h,   // [4*HID]
                   float* __restrict__ h_out,         // [B, HID, H, W]
                   int first)
{
    __shared__ float sp[ICC][PATCH][PATCH];  // input patches (with halo)
    __shared__ float sw[ICC][16][9];         // weights for 16 gate-channels

    const int tid = threadIdx.x;          // 0..255
    const int ty  = tid >> 4;             // 0..15
    const int tx  = tid & 15;             // 0..15
    const int tile = blockIdx.x;          // 0..3 (2x2 tiles of 32x32)
    const int ty0 = (tile >> 1) * TILE;
    const int tx0 = (tile & 1) * TILE;
    const int hid_base = blockIdx.y * 4;  // 4 hid channels per block
    const int b = blockIdx.z;

    float acc[16][4];                     // [gate*4 + j][pixel]
#pragma unroll
    for (int l = 0; l < 16; l++) {
        acc[l][0] = 0.f; acc[l][1] = 0.f; acc[l][2] = 0.f; acc[l][3] = 0.f;
    }

    const int icTotal = first ? CIN : (CIN + HID);

    for (int ic0 = 0; ic0 < icTotal; ic0 += ICC) {
        const float* src;
        const float* wsrc;
        int wnic, ch;
        if (ic0 < CIN) {
            src = x_t + (size_t)b * CIN * HH * WW;
            wsrc = w_x2h; wnic = CIN; ch = ic0;
        } else {
            src = h_prev + (size_t)b * HID * HH * WW;
            wsrc = w_h2h; wnic = HID; ch = ic0 - CIN;
        }
        const float* base = src + (size_t)ch * HH * WW;

        // cooperative patch load (zero-padded halo)
        for (int idx = tid; idx < ICC * PATCH * PATCH; idx += 256) {
            int ic = idx / (PATCH * PATCH);
            int r  = idx - ic * (PATCH * PATCH);
            int yy = r / PATCH;
            int xx = r - yy * PATCH;
            int gy = ty0 - 1 + yy;
            int gx = tx0 - 1 + xx;
            float v = 0.f;
            if ((unsigned)gy < (unsigned)HH && (unsigned)gx < (unsigned)WW)
                v = base[(size_t)ic * HH * WW + gy * WW + gx];
            sp[ic][yy][xx] = v;
        }
        // cooperative weight load: local l -> global oc = (l/4)*HID + hid_base + (l%4)
        for (int idx = tid; idx < ICC * 16 * 9; idx += 256) {
            int ic = idx / 144;
            int r  = idx - ic * 144;
            int l  = r / 9;
            int k  = r - l * 9;
            int oc = (l >> 2) * HID + hid_base + (l & 3);
            sw[ic][l][k] = wsrc[((size_t)oc * wnic + ch + ic) * 9 + k];
        }
        __syncthreads();

        for (int ic = 0; ic < ICC; ic++) {
            // 4x4 input footprint for this thread's 2x2 pixels
            float v[4][4];
#pragma unroll
            for (int a = 0; a < 4; a++)
#pragma unroll
                for (int c2 = 0; c2 < 4; c2++)
                    v[a][c2] = sp[ic][ty * 2 + a][tx * 2 + c2];

#pragma unroll
            for (int l = 0; l < 16; l++) {
                float w0 = sw[ic][l][0], w1 = sw[ic][l][1], w2 = sw[ic][l][2];
                float w3 = sw[ic][l][3], w4 = sw[ic][l][4], w5 = sw[ic][l][5];
                float w6 = sw[ic][l][6], w7 = sw[ic][l][7], w8 = sw[ic][l][8];
#pragma unroll
                for (int p = 0; p < 4; p++) {
                    const int py = p >> 1, px = p & 1;
                    float s = acc[l][p];
                    s += v[py + 0][px + 0] * w0;
                    s += v[py + 0][px + 1] * w1;
                    s += v[py + 0][px + 2] * w2;
                    s += v[py + 1][px + 0] * w3;
                    s += v[py + 1][px + 1] * w4;
                    s += v[py + 1][px + 2] * w5;
                    s += v[py + 2][px + 0] * w6;
                    s += v[py + 2][px + 1] * w7;
                    s += v[py + 2][px + 2] * w8;
                    acc[l][p] = s;
                }
            }
        }
        __syncthreads();
    }

    // LSTM epilogue: gate order i, f, g, o along channel dim (blocks of HID)
#pragma unroll
    for (int j = 0; j < 4; j++) {
        const int hid = hid_base + j;
        const float bI = b_x2h[0 * HID + hid] + b_h2h[0 * HID + hid];
        const float bF = b_x2h[1 * HID + hid] + b_h2h[1 * HID + hid];
        const float bG = b_x2h[2 * HID + hid] + b_h2h[2 * HID + hid];
        const float bO = b_x2h[3 * HID + hid] + b_h2h[3 * HID + hid];
#pragma unroll
        for (int p = 0; p < 4; p++) {
            const int y = ty0 + ty * 2 + (p >> 1);
            const int x = tx0 + tx * 2 + (p & 1);
            const size_t off = ((size_t)(b * HID + hid)) * HH * WW + (size_t)y * WW + x;
            float gi = sigmoidf_(acc[0 * 4 + j][p] + bI);
            float gf = sigmoidf_(acc[1 * 4 + j][p] + bF);
            float gg = tanhf    (acc[2 * 4 + j][p] + bG);
            float go = sigmoidf_(acc[3 * 4 + j][p] + bO);
            float cold = first ? 0.f : g_c[off];
            float cn = gf * cold + gi * gg;
            g_c[off]   = cn;
            h_out[off] = go * tanhf(cn);
        }
    }
}

extern "C" void kernel_launch(void* const* d_in, const int* in_sizes, int n_in,
                              void* d_out, int out_size)
{
    const float* x     = (const float*)d_in[0];  // [T,B,CIN,H,W]
    const float* w_x2h = (const float*)d_in[1];  // [4*HID,CIN,3,3]
    const float* b_x2h = (const float*)d_in[2];  // [4*HID]
    const float* w_h2h = (const float*)d_in[3];  // [4*HID,HID,3,3]
    const float* b_h2h = (const float*)d_in[4];  // [4*HID]
    float* out = (float*)d_out;                  // [T,B,HID,H,W]

    const size_t x_step = (size_t)B_ * CIN * HH * WW;
    const size_t h_step = (size_t)B_ * HID * HH * WW;

    dim3 grid(4, HID / 4, B_);   // spatial tiles, hid groups, batch
    for (int t = 0; t < T_; t++) {
        const float* x_t    = x + (size_t)t * x_step;
        const float* h_prev = (t == 0) ? x /*unused*/ : out + (size_t)(t - 1) * h_step;
        float* h_out        = out + (size_t)t * h_step;
        convlstm_step<<<grid, 256>>>(x_t, h_prev, w_x2h, w_h2h,
                                     b_x2h, b_h2h, h_out, t == 0 ? 1 : 0);
    }
}